// round 13
// baseline (speedup 1.0000x reference)
#include <cuda_runtime.h>
#include <cuda_bf16.h>
#include <cstdint>

// BahdanauAttention with size-1 attention axis:
//   softmax over length-1 axis == 1.0 -> attention_weights = ones(B,1,1)
//   context = features (bit-exact copy). Score GEMMs are dead code.
//
// Round-11/12 decomposition: CE DtoD memcpy moves the 128 MiB context in
// ~33.5us (== DRAM ideal, beats the 36.4us converged SM kernel), but a
// separate 3.4us fill KERNEL for the 64 KiB ones tail ate the win, and
// graph fork/join failed to hide it. This round: NO kernels at all.
// Two CE memcpy nodes: 128 MiB context + 64 KiB ones copied from a
// statically-initialized __device__ array (module global memory — the
// sanctioned scratch mechanism, no allocation).

static constexpr long long Bsz = 16384;
static constexpr long long Dsz = 2048;
static constexpr long long CTX_ELEMS = Bsz * Dsz;          // 33,554,432 floats
static constexpr long long CTX_BYTES = CTX_ELEMS * 4;      // 128 MiB
static constexpr long long AW_BYTES  = Bsz * 4;            // 64 KiB

// 16384 x 1.0f, preprocessor-expanded static initializer.
#define O8    1.f,1.f,1.f,1.f,1.f,1.f,1.f,1.f
#define O64   O8,O8,O8,O8,O8,O8,O8,O8
#define O512  O64,O64,O64,O64,O64,O64,O64,O64
#define O4096 O512,O512,O512,O512,O512,O512,O512,O512
__device__ float d_ones[16384] = { O4096, O4096, O4096, O4096 };

extern "C" void kernel_launch(void* const* d_in, const int* in_sizes, int n_in,
                              void* d_out, int out_size) {
    const float* features = (const float*)d_in[0];
    float* out = (float*)d_out;

    // Resolve the device address of the ones array once (host-side query,
    // capture-legal, does not change enqueued work).
    static void* ones_ptr = nullptr;
    if (ones_ptr == nullptr) {
        cudaGetSymbolAddress(&ones_ptr, d_ones);
    }

    // Bulk context copy on the copy engine.
    cudaMemcpyAsync(out, features, (size_t)CTX_BYTES,
                    cudaMemcpyDeviceToDevice, 0);
    // Attention-weights ones tail: tiny CE copy (~1us vs 3.4us kernel node).
    cudaMemcpyAsync(out + CTX_ELEMS, ones_ptr, (size_t)AW_BYTES,
                    cudaMemcpyDeviceToDevice, 0);
}

// round 14
// speedup vs baseline: 1.0489x; 1.0489x over previous
#include <cuda_runtime.h>
#include <cuda_bf16.h>
#include <cstdint>

// BahdanauAttention with size-1 attention axis:
//   softmax over length-1 axis == 1.0 -> attention_weights = ones(B,1,1)
//   context = features (bit-exact copy). Score GEMMs are dead code.
// Pure HBM streaming copy: 128 MiB read + 128 MiB write + 64 KiB fill.
//
// Conclusion from rounds 10-13: every multi-node graph scheme (CE memcpy,
// memcpy+kernel, fork/join, memcpy+memcpy) loses to the single fused SM
// kernel because per-node replay overhead (3-5us) exceeds any copy-path
// gain. Single kernel, ones folded in, is structurally optimal.
// This round: final scheduling knob — 512-thread blocks (same 2^19
// threads, 16 vec/thread true-MLP front-batch, regs~86 fits 1 block/SM).

static constexpr int Bsz = 16384;
static constexpr int Dsz = 2048;
static constexpr int CTX_VECS = (Bsz * Dsz) / 4;   // 8,388,608 float4 (2^23)
static constexpr int AW_VECS  = Bsz / 4;           // 4,096 float4

static constexpr int THREADS = 512;
static constexpr int BLOCKS  = 1024;
static constexpr int NTHREADS = THREADS * BLOCKS;           // 524,288 = 2^19
static constexpr int VECS_PER_THREAD = CTX_VECS / NTHREADS; // 16, exact

__global__ void __launch_bounds__(THREADS, 1)
bahdanau_copy_kernel(const float4* __restrict__ features, float4* __restrict__ out) {
    int tid = blockIdx.x * THREADS + threadIdx.x;

    // All 16 loads issued before any store (true MLP=16, regs ~86).
    float4 a[VECS_PER_THREAD];
    #pragma unroll
    for (int j = 0; j < VECS_PER_THREAD; j++)
        a[j] = features[tid + j * NTHREADS];
    #pragma unroll
    for (int j = 0; j < VECS_PER_THREAD; j++)
        out[tid + j * NTHREADS] = a[j];

    // Trailing ones for attention_weights: one extra store for 4096 threads.
    if (tid < AW_VECS) {
        out[CTX_VECS + tid] = make_float4(1.f, 1.f, 1.f, 1.f);
    }
}

extern "C" void kernel_launch(void* const* d_in, const int* in_sizes, int n_in,
                              void* d_out, int out_size) {
    const float4* features = (const float4*)d_in[0];
    float4* out = (float4*)d_out;
    bahdanau_copy_kernel<<<BLOCKS, THREADS>>>(features, out);
}

// round 15
// speedup vs baseline: 1.0497x; 1.0007x over previous
#include <cuda_runtime.h>
#include <cuda_bf16.h>
#include <cstdint>

// BahdanauAttention with size-1 attention axis:
//   softmax over length-1 axis == 1.0 -> attention_weights = ones(B,1,1)
//   context = features (bit-exact copy). Score GEMMs are dead code.
// Pure HBM streaming copy: 128 MiB read + 128 MiB write + 64 KiB fill.
//
// FINAL (round-7 champion, best measured e2e 45.088us, kernel 36.4us =
// 7.38 TB/s = 92% of HBM3e spec). Measured-converged across grid shape,
// MLP depth, occupancy, cache policy, access width, and copy-engine
// alternatives; single fused kernel beats all multi-node graph schemes
// because per-node replay overhead (3-5us) exceeds any copy-path gain.

static constexpr int Bsz = 16384;
static constexpr int Dsz = 2048;
static constexpr int CTX_VECS = (Bsz * Dsz) / 4;   // 8,388,608 float4 (2^23)
static constexpr int AW_VECS  = Bsz / 4;           // 4,096 float4

static constexpr int THREADS = 256;
static constexpr int BLOCKS  = 2048;
static constexpr int NTHREADS = THREADS * BLOCKS;           // 524,288 = 2^19
static constexpr int VECS_PER_THREAD = CTX_VECS / NTHREADS; // 16, exact

__global__ void __launch_bounds__(THREADS, 2)
bahdanau_copy_kernel(const float4* __restrict__ features, float4* __restrict__ out) {
    int tid = blockIdx.x * THREADS + threadIdx.x;

    // All 16 loads issued before any store (true MLP=16, regs ~86).
    float4 a[VECS_PER_THREAD];
    #pragma unroll
    for (int j = 0; j < VECS_PER_THREAD; j++)
        a[j] = features[tid + j * NTHREADS];
    #pragma unroll
    for (int j = 0; j < VECS_PER_THREAD; j++)
        out[tid + j * NTHREADS] = a[j];

    // Trailing ones for attention_weights: one extra store for 4096 threads.
    if (tid < AW_VECS) {
        out[CTX_VECS + tid] = make_float4(1.f, 1.f, 1.f, 1.f);
    }
}

extern "C" void kernel_launch(void* const* d_in, const int* in_sizes, int n_in,
                              void* d_out, int out_size) {
    const float4* features = (const float4*)d_in[0];
    float4* out = (float4*)d_out;
    bahdanau_copy_kernel<<<BLOCKS, THREADS>>>(features, out);
}